// round 16
// baseline (speedup 1.0000x reference)
#include <cuda_runtime.h>
#include <cuda_fp16.h>
#include <cstdint>

// out[16384,1280] = x[16384,1280] @ A[1280,1280],  A = (k1 (x) k2 (x) k3) @ W^T
// Kron factorization in fp32, then SINGLE-product fp16 HMMA GEMM:
//   D = fp16(x) * fp16(A^T)   (fp32 accumulate)  rel_err ~2.9e-4 (validated)
// R15: R13 fixed — XPITCHB 136 -> 144 (16B multiple) so every cp.async smem
// destination is 16-aligned (136 gave 8-aligned odd rows -> misaligned trap).
// GEMM reads fp32 x directly, builds fp16 A-fragments in registers.
// NSTAGE=4, 2 CTAs/SM (229376 B <= 228KB). A-chain unchanged (validated).

#define DD 1280
#define MROWS 16384

__device__ float g_buf0[DD * DD];
__device__ float g_buf1[DD * DD];
__device__ float g_k12[32 * 32];
__device__ __half g_Ath[DD * DD];   // fp16(A^T): [n][k], k contiguous

// ---------------------------------------------------------------------------
__device__ __forceinline__ uint32_t smem_u32(const void* p) {
    uint32_t a;
    asm("{ .reg .u64 t; cvta.to.shared.u64 t, %1; cvt.u32.u64 %0, t; }" : "=r"(a) : "l"(p));
    return a;
}
__device__ __forceinline__ void ldsm_x4(uint32_t* r, uint32_t addr) {
    asm volatile("ldmatrix.sync.aligned.m8n8.x4.shared.b16 {%0,%1,%2,%3}, [%4];"
                 : "=r"(r[0]), "=r"(r[1]), "=r"(r[2]), "=r"(r[3]) : "r"(addr));
}
__device__ __forceinline__ void mma_f16(float* c, const uint32_t* a, const uint32_t* b) {
    asm volatile("mma.sync.aligned.m16n8k16.row.col.f32.f16.f16.f32 "
                 "{%0,%1,%2,%3}, {%4,%5,%6,%7}, {%8,%9}, {%0,%1,%2,%3};"
                 : "+f"(c[0]), "+f"(c[1]), "+f"(c[2]), "+f"(c[3])
                 : "r"(a[0]), "r"(a[1]), "r"(a[2]), "r"(a[3]), "r"(b[0]), "r"(b[1]));
}
__device__ __forceinline__ uint32_t cvt_h2(float2 v) {
    __half2 h = __floats2half2_rn(v.x, v.y);
    return *reinterpret_cast<uint32_t*>(&h);
}
#define CP16(dst, src) \
    asm volatile("cp.async.cg.shared.global [%0], [%1], 16;" :: "r"(dst), "l"(src))
#define CP_COMMIT() asm volatile("cp.async.commit_group;" ::: "memory")
#define CP_WAIT2()  asm volatile("cp.async.wait_group 2;" ::: "memory")

// ---------------------------------------------------------------------------
// A-chain (fp32) — unchanged (validated R11/R12)
// ---------------------------------------------------------------------------
__global__ void transpose_kernel(const float* __restrict__ W, float* __restrict__ Wt) {
    __shared__ float tile[32][33];
    const int j0 = blockIdx.x * 32, o0 = blockIdx.y * 32;
    const int tx = threadIdx.x, ty = threadIdx.y;
#pragma unroll
    for (int r = 0; r < 32; r += 8)
        tile[ty + r][tx] = W[(o0 + ty + r) * DD + (j0 + tx)];
    __syncthreads();
#pragma unroll
    for (int r = 0; r < 32; r += 8)
        Wt[(j0 + ty + r) * DD + (o0 + tx)] = tile[tx][ty + r];
}
__global__ void kron12_kernel(const float* __restrict__ k1, const float* __restrict__ k2,
                              float* __restrict__ k12) {
    const int t = threadIdx.x;
    const int r = t >> 5, c = t & 31;
    k12[t] = k1[(r >> 3) * 4 + (c >> 3)] * k2[(r & 7) * 8 + (c & 7)];
}
__global__ __launch_bounds__(256)
void stage3_kernel(const float* __restrict__ src, float* __restrict__ dst,
                   const float* __restrict__ k3) {
    const int tid = threadIdx.x;
    const int o = blockIdx.x * 256 + tid;
    const int g = blockIdx.y / 5;
    const int a3b = (blockIdx.y % 5) * 8;

    __shared__ float sk[8][40];
    for (int i = tid; i < 320; i += 256)
        sk[i / 40][i % 40] = k3[(a3b + i / 40) * 40 + (i % 40)];
    __syncthreads();

    const float* s = src + (g * 40) * DD + o;
    float v[40];
#pragma unroll
    for (int b3 = 0; b3 < 40; b3++) v[b3] = s[b3 * DD];

#pragma unroll
    for (int j = 0; j < 8; j++) {
        float acc0 = 0.f, acc1 = 0.f;
#pragma unroll
        for (int b3 = 0; b3 < 40; b3 += 2) {
            acc0 += sk[j][b3] * v[b3];
            acc1 += sk[j][b3 + 1] * v[b3 + 1];
        }
        dst[(g * 40 + a3b + j) * DD + o] = acc0 + acc1;
    }
}
__global__ __launch_bounds__(256)
void stage12_kernel(const float* __restrict__ src, float* __restrict__ dst,
                    const float* __restrict__ k12) {
    const int tid = threadIdx.x;
    const int o = blockIdx.x * 256 + tid;
    const int a3 = blockIdx.y >> 2;
    const int cb = (blockIdx.y & 3) * 8;

    __shared__ float sk[8][32];
    if (tid < 256)
        sk[tid >> 5][tid & 31] = k12[(cb + (tid >> 5)) * 32 + (tid & 31)];
    __syncthreads();

    const float* s = src + a3 * DD + o;
    float v[32];
#pragma unroll
    for (int b12 = 0; b12 < 32; b12++) v[b12] = s[b12 * 40 * DD];

#pragma unroll
    for (int j = 0; j < 8; j++) {
        float acc0 = 0.f, acc1 = 0.f;
#pragma unroll
        for (int b12 = 0; b12 < 32; b12 += 2) {
            acc0 += sk[j][b12] * v[b12];
            acc1 += sk[j][b12 + 1] * v[b12 + 1];
        }
        dst[((cb + j) * 40 + a3) * DD + o] = acc0 + acc1;
    }
}
__global__ void cvt_at_kernel(const float* __restrict__ A, __half* __restrict__ ath) {
    __shared__ float t[32][33];
    const int k0 = blockIdx.x * 32, n0 = blockIdx.y * 32;
    const int tx = threadIdx.x, ty = threadIdx.y;
#pragma unroll
    for (int r = 0; r < 32; r += 8)
        t[ty + r][tx] = A[(k0 + ty + r) * DD + (n0 + tx)];
    __syncthreads();
#pragma unroll
    for (int r = 0; r < 32; r += 8)
        ath[(n0 + ty + r) * DD + (k0 + tx)] = __float2half_rn(t[tx][ty + r]);
}

// ---------------------------------------------------------------------------
// fp16 HMMA GEMM with in-kernel fp32->fp16 X conversion.
// CTA tile 128x128, BK=32, 256 threads, NSTAGE=4, 2 CTAs/SM, 1 barrier/ktile.
// X staged fp32 with 144B row pitch (16B-aligned cp.async, ~2-way LDS banks);
// A staged fp16 (80B rows, ldmatrix).
// ---------------------------------------------------------------------------
#define BK 32
#define XPITCHB 144                 // 32 floats (128B) + 16B pad -> 16B-aligned rows
#define XTB (128 * XPITCHB)         // 18432 B
#define PADK 40
#define ATB (128 * PADK * 2)        // 10240 B
#define STB (XTB + ATB)             // 28672 B
#define NSTAGE 4
#define GEMM_SMEM (NSTAGE * STB)    // 114688 B
#define KTILES (DD / BK)            // 40

__device__ __forceinline__ void load_stage_async(
    uint32_t sdst,
    const float* __restrict__ X, const __half* __restrict__ Ath,
    int bm, int bn, int kt, int tid) {
    const int kofs = kt * BK;
    // X fp32: 128 rows x 8 x 16B chunks
#pragma unroll
    for (int i = 0; i < 4; i++) {
        int idx = i * 256 + tid;          // 0..1023
        int row = idx >> 3, c = idx & 7;
        uint32_t so = (uint32_t)(row * XPITCHB + c * 16);
        size_t gx = (size_t)(bm * 128 + row) * DD + kofs + c * 4;
        CP16(sdst + so, X + gx);
    }
    // A fp16: 128 rows x 4 x 16B chunks
#pragma unroll
    for (int i = 0; i < 2; i++) {
        int idx = i * 256 + tid;          // 0..511
        int row = idx >> 2, c = idx & 3;
        uint32_t so = (uint32_t)(row * (PADK * 2) + c * 16);
        size_t ga = (size_t)(bn * 128 + row) * DD + kofs + c * 8;
        CP16(sdst + XTB + so, Ath + ga);
    }
}

__global__ __launch_bounds__(256, 2)
void gemm_hmma_kernel(const float* __restrict__ X,
                      const __half* __restrict__ Ath,
                      float* __restrict__ out) {
    extern __shared__ __align__(128) char smem[];
    const uint32_t sbase = smem_u32(smem);
    const int tid = threadIdx.x, lane = tid & 31, wid = tid >> 5;
    const int warp_m = wid & 3, warp_n = wid >> 2;   // 4 x 2 warps, tile 32x64
    const int bn = blockIdx.x, bm = blockIdx.y;

    float acc[2][8][4];
#pragma unroll
    for (int a = 0; a < 2; a++)
#pragma unroll
        for (int b = 0; b < 8; b++)
#pragma unroll
            for (int c = 0; c < 4; c++) acc[a][b][c] = 0.f;

#pragma unroll
    for (int p = 0; p < 3; p++) {
        load_stage_async(sbase + (uint32_t)p * STB, X, Ath, bm, bn, p, tid);
        CP_COMMIT();
    }

    // A-fragment lane map (m16n8k16, row-major A): row group lane>>2, k pair (lane&3)*2
    const int gr = lane >> 2;            // 0..7
    const int gc = (lane & 3) * 2;       // 0,2,4,6
    // B ldmatrix addressing (validated)
    const uint32_t b_nrow = (uint32_t)(warp_n * 64 + (lane & 7) + ((lane >> 4) & 1) * 8);
    const uint32_t b_kb = (uint32_t)(((lane >> 3) & 1) * 8) * 2;

    for (int kt = 0; kt < KTILES; kt++) {
        CP_WAIT2();
        __syncthreads();   // single barrier per ktile
        const uint32_t stoff = (uint32_t)(kt % NSTAGE) * STB;
        const char* sX = smem + stoff;
        const uint32_t sA = sbase + stoff + XTB;
#pragma unroll
        for (int kk = 0; kk < 2; kk++) {
            const int c0 = gc + kk * 16;
            uint32_t ax[2][4];
#pragma unroll
            for (int mi = 0; mi < 2; mi++) {
                const int r0 = warp_m * 32 + mi * 16 + gr;
                float2 p0 = *reinterpret_cast<const float2*>(sX + r0 * XPITCHB + c0 * 4);
                float2 p1 = *reinterpret_cast<const float2*>(sX + (r0 + 8) * XPITCHB + c0 * 4);
                float2 p2 = *reinterpret_cast<const float2*>(sX + r0 * XPITCHB + (c0 + 8) * 4);
                float2 p3 = *reinterpret_cast<const float2*>(sX + (r0 + 8) * XPITCHB + (c0 + 8) * 4);
                ax[mi][0] = cvt_h2(p0);
                ax[mi][1] = cvt_h2(p1);
                ax[mi][2] = cvt_h2(p2);
                ax[mi][3] = cvt_h2(p3);
            }
            const uint32_t bcol = b_kb + kk * 32;
            uint32_t bb[8][2];
#pragma unroll
            for (int j = 0; j < 4; j++) {
                uint32_t r[4];
                ldsm_x4(r, sA + (b_nrow + j * 16) * (PADK * 2) + bcol);
                bb[2 * j][0] = r[0]; bb[2 * j][1] = r[1];
                bb[2 * j + 1][0] = r[2]; bb[2 * j + 1][1] = r[3];
            }
#pragma unroll
            for (int mi = 0; mi < 2; mi++)
#pragma unroll
                for (int nj = 0; nj < 8; nj++)
                    mma_f16(acc[mi][nj], ax[mi], bb[nj]);
        }
        if (kt + 3 < KTILES)
            load_stage_async(sbase + (uint32_t)((kt + 3) % NSTAGE) * STB,
                             X, Ath, bm, bn, kt + 3, tid);
        CP_COMMIT();   // unconditional: keeps wait_group(2) retiring correctly
    }

    // epilogue
    const int er = lane >> 2, ec = (lane & 3) * 2;
#pragma unroll
    for (int mi = 0; mi < 2; mi++) {
        const int row = bm * 128 + warp_m * 32 + mi * 16 + er;
#pragma unroll
        for (int nt = 0; nt < 8; nt++) {
            const int col = bn * 128 + warp_n * 64 + nt * 8 + ec;
            *reinterpret_cast<float2*>(out + (size_t)row * DD + col) =
                make_float2(acc[mi][nt][0], acc[mi][nt][1]);
            *reinterpret_cast<float2*>(out + (size_t)(row + 8) * DD + col) =
                make_float2(acc[mi][nt][2], acc[mi][nt][3]);
        }
    }
}

// ---------------------------------------------------------------------------
extern "C" void kernel_launch(void* const* d_in, const int* in_sizes, int n_in,
                              void* d_out, int out_size) {
    const float* x  = (const float*)d_in[0];
    const float* W  = (const float*)d_in[1];
    const float* k1 = (const float*)d_in[2];
    const float* k2 = (const float*)d_in[3];
    const float* k3 = (const float*)d_in[4];
    float* out = (float*)d_out;

    float *buf0, *buf1, *k12;
    __half *ath;
    cudaGetSymbolAddress((void**)&buf0, g_buf0);
    cudaGetSymbolAddress((void**)&buf1, g_buf1);
    cudaGetSymbolAddress((void**)&k12, g_k12);
    cudaGetSymbolAddress((void**)&ath, g_Ath);

    static bool attr_set = false;
    if (!attr_set) {
        cudaFuncSetAttribute(gemm_hmma_kernel,
                             cudaFuncAttributeMaxDynamicSharedMemorySize, GEMM_SMEM);
        attr_set = true;
    }

    kron12_kernel<<<1, 1024>>>(k1, k2, k12);
    {
        dim3 grid(DD / 32, DD / 32), block(32, 8);
        transpose_kernel<<<grid, block>>>(W, buf0);
    }
    {
        dim3 g3(DD / 256, 32 * 5);
        stage3_kernel<<<g3, 256>>>(buf0, buf1, k3);     // buf1 = T1
        dim3 g12(DD / 256, 40 * 4);
        stage12_kernel<<<g12, 256>>>(buf1, buf0, k12);  // buf0 = A
    }
    {
        dim3 grid(DD / 32, DD / 32), block(32, 8);
        cvt_at_kernel<<<grid, block>>>(buf0, ath);
    }
    {
        dim3 grid(DD / 128, MROWS / 128);   // (10, 128)
        gemm_hmma_kernel<<<grid, 256, GEMM_SMEM>>>(x, ath, out);
    }
}

// round 17
// speedup vs baseline: 1.2571x; 1.2571x over previous
#include <cuda_runtime.h>
#include <cuda_fp16.h>
#include <cstdint>

// out[16384,1280] = x[16384,1280] @ A[1280,1280],  A = (k1 (x) k2 (x) k3) @ W^T
// Kron factorization in fp32, then SINGLE-product fp16 HMMA GEMM:
//   D = fp16(x) * fp16(A^T)   (fp32 accumulate)  rel_err ~2.9e-4 (validated)
// R16: revert to R12 structure (separate cvt_x + ldmatrix GEMM — R15 proved
// in-GEMM conversion blows the smem crossbar). GEMM: BK=64 (half the
// barriers), NSTAGE=3, prefetch issued BEFORE the MMA loop.

#define DD 1280
#define MROWS 16384

__device__ float g_buf0[DD * DD];
__device__ float g_buf1[DD * DD];
__device__ float g_k12[32 * 32];
__device__ __half g_Xh[(size_t)MROWS * DD];
__device__ __half g_Ath[DD * DD];   // fp16(A^T): [n][k], k contiguous

// ---------------------------------------------------------------------------
__device__ __forceinline__ uint32_t smem_u32(const void* p) {
    uint32_t a;
    asm("{ .reg .u64 t; cvta.to.shared.u64 t, %1; cvt.u32.u64 %0, t; }" : "=r"(a) : "l"(p));
    return a;
}
__device__ __forceinline__ void ldsm_x4(uint32_t* r, uint32_t addr) {
    asm volatile("ldmatrix.sync.aligned.m8n8.x4.shared.b16 {%0,%1,%2,%3}, [%4];"
                 : "=r"(r[0]), "=r"(r[1]), "=r"(r[2]), "=r"(r[3]) : "r"(addr));
}
__device__ __forceinline__ void mma_f16(float* c, const uint32_t* a, const uint32_t* b) {
    asm volatile("mma.sync.aligned.m16n8k16.row.col.f32.f16.f16.f32 "
                 "{%0,%1,%2,%3}, {%4,%5,%6,%7}, {%8,%9}, {%0,%1,%2,%3};"
                 : "+f"(c[0]), "+f"(c[1]), "+f"(c[2]), "+f"(c[3])
                 : "r"(a[0]), "r"(a[1]), "r"(a[2]), "r"(a[3]), "r"(b[0]), "r"(b[1]));
}
#define CP16(dst, src) \
    asm volatile("cp.async.cg.shared.global [%0], [%1], 16;" :: "r"(dst), "l"(src))
#define CP_COMMIT() asm volatile("cp.async.commit_group;" ::: "memory")
#define CP_WAIT1()  asm volatile("cp.async.wait_group 1;" ::: "memory")

// ---------------------------------------------------------------------------
// A-chain (fp32) — validated R11/R12
// ---------------------------------------------------------------------------
__global__ void transpose_kernel(const float* __restrict__ W, float* __restrict__ Wt) {
    __shared__ float tile[32][33];
    const int j0 = blockIdx.x * 32, o0 = blockIdx.y * 32;
    const int tx = threadIdx.x, ty = threadIdx.y;
#pragma unroll
    for (int r = 0; r < 32; r += 8)
        tile[ty + r][tx] = W[(o0 + ty + r) * DD + (j0 + tx)];
    __syncthreads();
#pragma unroll
    for (int r = 0; r < 32; r += 8)
        Wt[(j0 + ty + r) * DD + (o0 + tx)] = tile[tx][ty + r];
}
__global__ void kron12_kernel(const float* __restrict__ k1, const float* __restrict__ k2,
                              float* __restrict__ k12) {
    const int t = threadIdx.x;
    const int r = t >> 5, c = t & 31;
    k12[t] = k1[(r >> 3) * 4 + (c >> 3)] * k2[(r & 7) * 8 + (c & 7)];
}
__global__ __launch_bounds__(256)
void stage3_kernel(const float* __restrict__ src, float* __restrict__ dst,
                   const float* __restrict__ k3) {
    const int tid = threadIdx.x;
    const int o = blockIdx.x * 256 + tid;
    const int g = blockIdx.y / 5;
    const int a3b = (blockIdx.y % 5) * 8;

    __shared__ float sk[8][40];
    for (int i = tid; i < 320; i += 256)
        sk[i / 40][i % 40] = k3[(a3b + i / 40) * 40 + (i % 40)];
    __syncthreads();

    const float* s = src + (g * 40) * DD + o;
    float v[40];
#pragma unroll
    for (int b3 = 0; b3 < 40; b3++) v[b3] = s[b3 * DD];

#pragma unroll
    for (int j = 0; j < 8; j++) {
        float acc0 = 0.f, acc1 = 0.f;
#pragma unroll
        for (int b3 = 0; b3 < 40; b3 += 2) {
            acc0 += sk[j][b3] * v[b3];
            acc1 += sk[j][b3 + 1] * v[b3 + 1];
        }
        dst[(g * 40 + a3b + j) * DD + o] = acc0 + acc1;
    }
}
__global__ __launch_bounds__(256)
void stage12_kernel(const float* __restrict__ src, float* __restrict__ dst,
                    const float* __restrict__ k12) {
    const int tid = threadIdx.x;
    const int o = blockIdx.x * 256 + tid;
    const int a3 = blockIdx.y >> 2;
    const int cb = (blockIdx.y & 3) * 8;

    __shared__ float sk[8][32];
    if (tid < 256)
        sk[tid >> 5][tid & 31] = k12[(cb + (tid >> 5)) * 32 + (tid & 31)];
    __syncthreads();

    const float* s = src + a3 * DD + o;
    float v[32];
#pragma unroll
    for (int b12 = 0; b12 < 32; b12++) v[b12] = s[b12 * 40 * DD];

#pragma unroll
    for (int j = 0; j < 8; j++) {
        float acc0 = 0.f, acc1 = 0.f;
#pragma unroll
        for (int b12 = 0; b12 < 32; b12 += 2) {
            acc0 += sk[j][b12] * v[b12];
            acc1 += sk[j][b12 + 1] * v[b12 + 1];
        }
        dst[((cb + j) * 40 + a3) * DD + o] = acc0 + acc1;
    }
}
// x -> fp16, 8 elems/thread
__global__ void cvt_x_kernel(const float* __restrict__ x, __half* __restrict__ xh) {
    const size_t i8 = ((size_t)blockIdx.x * 256 + threadIdx.x) * 8;
    float4 v0 = *reinterpret_cast<const float4*>(x + i8);
    float4 v1 = *reinterpret_cast<const float4*>(x + i8 + 4);
    __half2 a = __floats2half2_rn(v0.x, v0.y);
    __half2 b = __floats2half2_rn(v0.z, v0.w);
    __half2 c = __floats2half2_rn(v1.x, v1.y);
    __half2 d = __floats2half2_rn(v1.z, v1.w);
    uint4 o;
    o.x = *reinterpret_cast<uint32_t*>(&a);
    o.y = *reinterpret_cast<uint32_t*>(&b);
    o.z = *reinterpret_cast<uint32_t*>(&c);
    o.w = *reinterpret_cast<uint32_t*>(&d);
    *reinterpret_cast<uint4*>(xh + i8) = o;
}
__global__ void cvt_at_kernel(const float* __restrict__ A, __half* __restrict__ ath) {
    __shared__ float t[32][33];
    const int k0 = blockIdx.x * 32, n0 = blockIdx.y * 32;
    const int tx = threadIdx.x, ty = threadIdx.y;
#pragma unroll
    for (int r = 0; r < 32; r += 8)
        t[ty + r][tx] = A[(k0 + ty + r) * DD + (n0 + tx)];
    __syncthreads();
#pragma unroll
    for (int r = 0; r < 32; r += 8)
        ath[(n0 + ty + r) * DD + (k0 + tx)] = __float2half_rn(t[tx][ty + r]);
}

// ---------------------------------------------------------------------------
// fp16 HMMA GEMM. CTA tile 128x128, BK=64, 256 threads, NSTAGE=3, 2 CTAs/SM,
// one barrier per 64-K tile; prefetch issued before the MMA loop.
// smem rows: 64 halves data + 8 pad = 72 halves (144 B) — ldmatrix
// conflict-free (9r mod 8 spans all bank groups).
// ---------------------------------------------------------------------------
#define BK 64
#define PADK 72
#define TPITCH (PADK * 2)           // 144 B
#define XTB (128 * TPITCH)          // 18432 B
#define STB (2 * XTB)               // 36864 B
#define NSTAGE 3
#define GEMM_SMEM (NSTAGE * STB)    // 110592 B
#define KTILES (DD / BK)            // 20

__device__ __forceinline__ void load_stage_async(
    uint32_t sdst,
    const __half* __restrict__ Xh, const __half* __restrict__ Ath,
    int bm, int bn, int kt, int tid) {
    const int kofs = kt * BK;
    // 128 rows x 8 x 16B chunks each for X and A
#pragma unroll
    for (int i = 0; i < 4; i++) {
        int idx = i * 256 + tid;          // 0..1023
        int row = idx >> 3, c = idx & 7;
        uint32_t so = (uint32_t)(row * TPITCH + c * 16);
        size_t gx = (size_t)(bm * 128 + row) * DD + kofs + c * 8;
        size_t ga = (size_t)(bn * 128 + row) * DD + kofs + c * 8;
        CP16(sdst + so,       Xh  + gx);
        CP16(sdst + XTB + so, Ath + ga);
    }
}

__global__ __launch_bounds__(256, 2)
void gemm_hmma_kernel(const __half* __restrict__ Xh,
                      const __half* __restrict__ Ath,
                      float* __restrict__ out) {
    extern __shared__ __align__(128) char smem[];
    const uint32_t sbase = smem_u32(smem);
    const int tid = threadIdx.x, lane = tid & 31, wid = tid >> 5;
    const int warp_m = wid & 3, warp_n = wid >> 2;   // 4 x 2 warps, tile 32x64
    const int bn = blockIdx.x, bm = blockIdx.y;

    float acc[2][8][4];
#pragma unroll
    for (int a = 0; a < 2; a++)
#pragma unroll
        for (int b = 0; b < 8; b++)
#pragma unroll
            for (int c = 0; c < 4; c++) acc[a][b][c] = 0.f;

    load_stage_async(sbase, Xh, Ath, bm, bn, 0, tid);
    CP_COMMIT();
    load_stage_async(sbase + STB, Xh, Ath, bm, bn, 1, tid);
    CP_COMMIT();

    const uint32_t a_row = (uint32_t)(warp_m * 32 + (lane & 7) + ((lane >> 3) & 1) * 8);
    const uint32_t a_colb = (uint32_t)(((lane >> 4) & 1) * 8) * 2;
    const uint32_t b_nrow = (uint32_t)(warp_n * 64 + (lane & 7) + ((lane >> 4) & 1) * 8);
    const uint32_t b_kb = (uint32_t)(((lane >> 3) & 1) * 8) * 2;

    for (int kt = 0; kt < KTILES; kt++) {
        CP_WAIT1();
        __syncthreads();   // stage (kt+2)%3 (written next) was last read at kt-1
        // Prefetch FIRST: a full ktile of compute covers the load latency.
        if (kt + 2 < KTILES)
            load_stage_async(sbase + (uint32_t)((kt + 2) % NSTAGE) * STB,
                             Xh, Ath, bm, bn, kt + 2, tid);
        CP_COMMIT();       // unconditional: keeps wait_group(1) retiring correctly

        const uint32_t st = sbase + (uint32_t)(kt % NSTAGE) * STB;
        const uint32_t sX = st, sA = st + XTB;
#pragma unroll
        for (int kk = 0; kk < 4; kk++) {
            const uint32_t acol = a_colb + kk * 32;   // kk*16 elems * 2B
            const uint32_t bcol = b_kb + kk * 32;
            uint32_t ax[2][4];
            ldsm_x4(ax[0], sX + a_row * TPITCH + acol);
            ldsm_x4(ax[1], sX + (a_row + 16) * TPITCH + acol);
            uint32_t bb[8][2];
#pragma unroll
            for (int j = 0; j < 4; j++) {
                uint32_t r[4];
                ldsm_x4(r, sA + (b_nrow + j * 16) * TPITCH + bcol);
                bb[2 * j][0] = r[0]; bb[2 * j][1] = r[1];
                bb[2 * j + 1][0] = r[2]; bb[2 * j + 1][1] = r[3];
            }
#pragma unroll
            for (int mi = 0; mi < 2; mi++)
#pragma unroll
                for (int nj = 0; nj < 8; nj++)
                    mma_f16(acc[mi][nj], ax[mi], bb[nj]);
        }
    }

    // epilogue
    const int er = lane >> 2, ec = (lane & 3) * 2;
#pragma unroll
    for (int mi = 0; mi < 2; mi++) {
        const int row = bm * 128 + warp_m * 32 + mi * 16 + er;
#pragma unroll
        for (int nt = 0; nt < 8; nt++) {
            const int col = bn * 128 + warp_n * 64 + nt * 8 + ec;
            *reinterpret_cast<float2*>(out + (size_t)row * DD + col) =
                make_float2(acc[mi][nt][0], acc[mi][nt][1]);
            *reinterpret_cast<float2*>(out + (size_t)(row + 8) * DD + col) =
                make_float2(acc[mi][nt][2], acc[mi][nt][3]);
        }
    }
}

// ---------------------------------------------------------------------------
extern "C" void kernel_launch(void* const* d_in, const int* in_sizes, int n_in,
                              void* d_out, int out_size) {
    const float* x  = (const float*)d_in[0];
    const float* W  = (const float*)d_in[1];
    const float* k1 = (const float*)d_in[2];
    const float* k2 = (const float*)d_in[3];
    const float* k3 = (const float*)d_in[4];
    float* out = (float*)d_out;

    float *buf0, *buf1, *k12;
    __half *xh, *ath;
    cudaGetSymbolAddress((void**)&buf0, g_buf0);
    cudaGetSymbolAddress((void**)&buf1, g_buf1);
    cudaGetSymbolAddress((void**)&k12, g_k12);
    cudaGetSymbolAddress((void**)&xh, g_Xh);
    cudaGetSymbolAddress((void**)&ath, g_Ath);

    static cudaStream_t s2 = nullptr;
    static cudaEvent_t ev_fork = nullptr, ev_join = nullptr;
    static bool attr_set = false;
    if (!attr_set) {
        cudaFuncSetAttribute(gemm_hmma_kernel,
                             cudaFuncAttributeMaxDynamicSharedMemorySize, GEMM_SMEM);
        cudaStreamCreateWithFlags(&s2, cudaStreamNonBlocking);
        cudaEventCreateWithFlags(&ev_fork, cudaEventDisableTiming);
        cudaEventCreateWithFlags(&ev_join, cudaEventDisableTiming);
        attr_set = true;
    }

    // Fork: cvt_x on s2, concurrent with A-chain.
    cudaEventRecord(ev_fork, 0);
    cudaStreamWaitEvent(s2, ev_fork, 0);
    {
        size_t n8 = (size_t)MROWS * DD / 8;
        cvt_x_kernel<<<(unsigned)(n8 / 256), 256, 0, s2>>>(x, xh);
    }
    cudaEventRecord(ev_join, s2);

    // A-chain on the main (capture) stream.
    kron12_kernel<<<1, 1024>>>(k1, k2, k12);
    {
        dim3 grid(DD / 32, DD / 32), block(32, 8);
        transpose_kernel<<<grid, block>>>(W, buf0);
    }
    {
        dim3 g3(DD / 256, 32 * 5);
        stage3_kernel<<<g3, 256>>>(buf0, buf1, k3);     // buf1 = T1
        dim3 g12(DD / 256, 40 * 4);
        stage12_kernel<<<g12, 256>>>(buf1, buf0, k12);  // buf0 = A
    }
    {
        dim3 grid(DD / 32, DD / 32), block(32, 8);
        cvt_at_kernel<<<grid, block>>>(buf0, ath);
    }

    // Join, then GEMM.
    cudaStreamWaitEvent(0, ev_join, 0);
    {
        dim3 grid(DD / 128, MROWS / 128);   // (10, 128)
        gemm_hmma_kernel<<<grid, 256, GEMM_SMEM>>>(xh, ath, out);
    }
}